// round 9
// baseline (speedup 1.0000x reference)
#include <cuda_runtime.h>

// metaCLF R7: R5 structure (V=2 packed-f32x2, 2-kernel split, 128-thr
// blocks, fully-unrolled G1) + R6's register trim (e[3][3] storage,
// pij recomputed) WITHOUT the unroll-1 pessimization, capped at
// launch_bounds(128,3) for 12 warps/SM.

typedef unsigned long long u64;

#define HWD   (96*96*96)   // 884736
#define NQUAD (HWD/4)      // 221184 quads (4 voxels) per batch
#define NB    2
#define TPB   128

// scratch for y = G3^T x  (static __device__ array: allowed)
__device__ float y_buf[(long long)NB * 64 * HWD];

__device__ __forceinline__ u64 bc2(float w) {
    u64 r; asm("mov.b64 %0, {%1, %2};" : "=l"(r) : "f"(w), "f"(w)); return r;
}
__device__ __forceinline__ u64 fma2(u64 a, u64 b, u64 c) {
    u64 d; asm("fma.rn.f32x2 %0, %1, %2, %3;" : "=l"(d) : "l"(a), "l"(b), "l"(c)); return d;
}
__device__ __forceinline__ u64 mul2(u64 a, u64 b) {
    u64 d; asm("mul.rn.f32x2 %0, %1, %2;" : "=l"(d) : "l"(a), "l"(b)); return d;
}
__device__ __forceinline__ u64 add2(u64 a, u64 b) {
    u64 d; asm("add.rn.f32x2 %0, %1, %2;" : "=l"(d) : "l"(a), "l"(b)); return d;
}
__device__ __forceinline__ u64 relu2(u64 a) {
    float lo, hi;
    asm("mov.b64 {%0, %1}, %2;" : "=f"(lo), "=f"(hi) : "l"(a));
    lo = fmaxf(lo, 0.0f); hi = fmaxf(hi, 0.0f);
    u64 r; asm("mov.b64 %0, {%1, %2};" : "=l"(r) : "f"(lo), "f"(hi));
    return r;
}
__device__ __forceinline__ void lds2(const u64* p, u64& a, u64& b) {
    unsigned long long sp = __cvta_generic_to_shared(p);
    asm("ld.shared.v2.b64 {%0, %1}, [%2];" : "=l"(a), "=l"(b) : "l"(sp));
}

// ===================== Kernel Y: y = G3^T x =====================
__global__ void __launch_bounds__(TPB, 3)
y_kernel(const float* __restrict__ x, const float* __restrict__ G3)
{
    __shared__ __align__(16) u64 sG3t[2048];   // [k][c] packed {w,w}
    for (int i = threadIdx.x; i < 2048; i += TPB) {
        int k = i >> 5, c = i & 31;
        sG3t[i] = bc2(G3[c * 64 + k]);
    }
    __syncthreads();

    const int q = blockIdx.x * TPB + threadIdx.x;    // quad index (exact grid)
    const int b = q / NQUAD;
    const long long v = (long long)(q - b * NQUAD) * 4;

    const float* xb = x + (long long)b * 32 * HWD + v;
    u64 xA[32], xB[32];
#pragma unroll
    for (int c = 0; c < 32; ++c) {
        ulonglong2 p = *(const ulonglong2*)(xb + (long long)c * HWD);
        xA[c] = p.x; xB[c] = p.y;
    }

    float* yb = y_buf + (long long)b * 64 * HWD + v;
#pragma unroll 4
    for (int k = 0; k < 64; ++k) {
        const u64* row = sG3t + k * 32;
        u64 sA0 = 0, sA1 = 0, sB0 = 0, sB1 = 0;
#pragma unroll
        for (int c = 0; c < 32; c += 2) {
            u64 w0, w1; lds2(row + c, w0, w1);
            sA0 = fma2(w0, xA[c],     sA0);
            sB0 = fma2(w0, xB[c],     sB0);
            sA1 = fma2(w1, xA[c + 1], sA1);
            sB1 = fma2(w1, xB[c + 1], sB1);
        }
        ulonglong2 o; o.x = add2(sA0, sA1); o.y = add2(sB0, sB1);
        *(ulonglong2*)(yb + (long long)k * HWD) = o;
    }
}

// ============ Kernel F: encode->G1->G2 + fused dot with y ============
// smem layout (u64 units): W1 @0 [32], W2T @32 [64], G1T @96 [27*32], G2 @960 [64*32]
#define FOFF_W1   0
#define FOFF_W2T  32
#define FOFF_G1T  96
#define FOFF_G2   960
#define FSW_TOT   3008

__global__ void __launch_bounds__(TPB, 3)
f_kernel(const float* __restrict__ d_all,
         const float* __restrict__ W1, const float* __restrict__ W2,
         const float* __restrict__ G1, const float* __restrict__ G2,
         float* __restrict__ out)
{
    __shared__ __align__(16) u64 sw[FSW_TOT];
    {
        const int t = threadIdx.x;
        for (int i = t; i < 32; i += TPB) sw[FOFF_W1 + i] = bc2(W1[i]);
        for (int i = t; i < 64; i += TPB) {
            int j = i >> 2, o = i & 3;
            sw[FOFF_W2T + i] = (o < 3) ? bc2(W2[o * 16 + j]) : 0ull;
        }
        for (int i = t; i < 864; i += TPB) {
            int e = i >> 5, c = i & 31;                 // G1T [e][c]
            sw[FOFF_G1T + i] = bc2(G1[c * 27 + e]);
        }
        for (int i = t; i < 2048; i += TPB) sw[FOFF_G2 + i] = bc2(G2[i]);
    }
    __syncthreads();
    const u64* sW1  = sw + FOFF_W1;
    const u64* sW2t = sw + FOFF_W2T;
    const u64* sG1t = sw + FOFF_G1T;
    const u64* sG2  = sw + FOFF_G2;

    const int q = blockIdx.x * TPB + threadIdx.x;
    const int b = q / NQUAD;
    const long long v = (long long)(q - b * NQUAD) * 4;

    // ---- encode both pairs (weights shared across pairs) ----
    const float* db = d_all + (long long)b * 6 * HWD + v;
    u64 eA[3][3], eB[3][3];
#pragma unroll
    for (int a = 0; a < 3; ++a) {
        ulonglong2 r0 = *(const ulonglong2*)(db + (long long)(2 * a + 0) * HWD);
        ulonglong2 r1 = *(const ulonglong2*)(db + (long long)(2 * a + 1) * HWD);
        const u64 dA0 = r0.x, dB0 = r0.y, dA1 = r1.x, dB1 = r1.y;
        u64 aA0 = 0, aA1 = 0, aA2 = 0, aB0 = 0, aB1 = 0, aB2 = 0;
#pragma unroll
        for (int j = 0; j < 16; ++j) {
            u64 w10, w11; lds2(sW1 + 2 * j, w10, w11);
            u64 tA = relu2(fma2(w10, dA0, mul2(w11, dA1)));
            u64 tB = relu2(fma2(w10, dB0, mul2(w11, dB1)));
            u64 w20, w21; lds2(sW2t + 4 * j, w20, w21);
            const u64 w22 = sW2t[4 * j + 2];
            aA0 = fma2(w20, tA, aA0);  aB0 = fma2(w20, tB, aB0);
            aA1 = fma2(w21, tA, aA1);  aB1 = fma2(w21, tB, aB1);
            aA2 = fma2(w22, tA, aA2);  aB2 = fma2(w22, tB, aB2);
        }
        eA[a][0] = aA0; eA[a][1] = aA1; eA[a][2] = aA2;
        eB[a][0] = aB0; eB[a][1] = aB1; eB[a][2] = aB2;
    }

    // ---- G1, e-major; kron partials recomputed (regs), fully unrolled ----
    u64 hA[32], hB[32];
#pragma unroll
    for (int c = 0; c < 32; ++c) { hA[c] = 0ull; hB[c] = 0ull; }
#pragma unroll 3
    for (int ij = 0; ij < 9; ++ij) {
        const u64 pA = mul2(eA[0][ij / 3], eA[1][ij % 3]);
        const u64 pB = mul2(eB[0][ij / 3], eB[1][ij % 3]);
#pragma unroll
        for (int kk = 0; kk < 3; ++kk) {
            const u64 encA = mul2(pA, eA[2][kk]);
            const u64 encB = mul2(pB, eB[2][kk]);
            const u64* row = sG1t + (ij * 3 + kk) * 32;
#pragma unroll
            for (int c = 0; c < 32; c += 2) {
                u64 w0, w1; lds2(row + c, w0, w1);
                hA[c]     = fma2(w0, encA, hA[c]);
                hB[c]     = fma2(w0, encB, hB[c]);
                hA[c + 1] = fma2(w1, encA, hA[c + 1]);
                hB[c + 1] = fma2(w1, encB, hB[c + 1]);
            }
        }
    }
#pragma unroll
    for (int c = 0; c < 32; ++c) { hA[c] = relu2(hA[c]); hB[c] = relu2(hB[c]); }

    // ---- k-loop: out += relu(G2[k]·h) * y_k ----
    const float* yb = y_buf + (long long)b * 64 * HWD + v;
    u64 accA = 0ull, accB = 0ull;
#pragma unroll 4
    for (int k = 0; k < 64; ++k) {
        const u64* row = sG2 + k * 32;
        // early y load so gmem latency overlaps the dot product
        ulonglong2 y2 = *(const ulonglong2*)(yb + (long long)k * HWD);
        u64 sA0 = 0, sA1 = 0, sB0 = 0, sB1 = 0;
#pragma unroll
        for (int c = 0; c < 32; c += 2) {
            u64 w0, w1; lds2(row + c, w0, w1);
            sA0 = fma2(w0, hA[c],     sA0);
            sB0 = fma2(w0, hB[c],     sB0);
            sA1 = fma2(w1, hA[c + 1], sA1);
            sB1 = fma2(w1, hB[c + 1], sB1);
        }
        const u64 hkA = relu2(add2(sA0, sA1));
        const u64 hkB = relu2(add2(sB0, sB1));
        accA = fma2(hkA, y2.x, accA);
        accB = fma2(hkB, y2.y, accB);
    }

    ulonglong2 o; o.x = accA; o.y = accB;
    *(ulonglong2*)(out + (long long)b * HWD + v) = o;
}

extern "C" void kernel_launch(void* const* d_in, const int* in_sizes, int n_in,
                              void* d_out, int out_size)
{
    const float* x    = (const float*)d_in[0];
    const float* dall = (const float*)d_in[1];
    const float* W1   = (const float*)d_in[2];
    const float* W2   = (const float*)d_in[3];
    const float* G1   = (const float*)d_in[4];
    const float* G2   = (const float*)d_in[5];
    const float* G3   = (const float*)d_in[6];
    float* out = (float*)d_out;

    const int total_threads = NB * NQUAD;      // 442368 = 3456 * 128
    dim3 grid(total_threads / TPB);
    y_kernel<<<grid, TPB>>>(x, G3);
    f_kernel<<<grid, TPB>>>(dall, W1, W2, G1, G2, out);
}

// round 11
// speedup vs baseline: 1.7056x; 1.7056x over previous
#include <cuda_runtime.h>
#include <cuda_bf16.h>

typedef unsigned int u32; typedef unsigned short u16; typedef unsigned long long u64;

#define HWD    (96*96*96)
#define TILESB (HWD/128)     // 6912
#define TILES  (2*TILESB)    // 13824
#define TPC    8
#define GRID_X (TILES/TPC)   // 1728
#define RSB    144           // A row stride in bytes (64 bf16 + 16B pad)

// smem byte offsets
#define SM_W   0
#define SM_AX  1024
#define SM_AE  19456
#define SM_B1  37888
#define SM_B2  46080
#define SM_B3  62464
#define SM_TOT 78848

static __device__ __forceinline__ u32 su32(const void* p) {
    return (u32)__cvta_generic_to_shared((void*)p);
}
static __device__ __forceinline__ void ldm4(u32* r, u32 addr) {
    asm volatile("ldmatrix.sync.aligned.m8n8.x4.shared.b16 {%0,%1,%2,%3}, [%4];"
        : "=r"(r[0]), "=r"(r[1]), "=r"(r[2]), "=r"(r[3]) : "r"(addr));
}
static __device__ __forceinline__ void mma16816(float* c, const u32* a, u32 b0, u32 b1) {
    asm volatile("mma.sync.aligned.m16n8k16.row.col.f32.bf16.bf16.f32 "
        "{%0,%1,%2,%3}, {%4,%5,%6,%7}, {%8,%9}, {%0,%1,%2,%3};"
        : "+f"(c[0]), "+f"(c[1]), "+f"(c[2]), "+f"(c[3])
        : "r"(a[0]), "r"(a[1]), "r"(a[2]), "r"(a[3]), "r"(b0), "r"(b1));
}
static __device__ __forceinline__ u16 bhi(float v) {
    return __bfloat16_as_ushort(__float2bfloat16_rn(v));
}
static __device__ __forceinline__ u16 blo(float v) {
    float r = v - __bfloat162float(__float2bfloat16_rn(v));
    return __bfloat16_as_ushort(__float2bfloat16_rn(r));
}
static __device__ __forceinline__ u32 packhi(float a, float b) {
    return (u32)bhi(a) | ((u32)bhi(b) << 16);
}
static __device__ __forceinline__ u32 packlo(float a, float b) {
    return (u32)blo(a) | ((u32)blo(b) << 16);
}
// write one A row: [hi(v0..31) | lo(v0..31)] bf16, 8x STS.128
static __device__ __forceinline__ void arow(char* base, int row, const float* v) {
    u32 q[32];
#pragma unroll
    for (int i = 0; i < 16; ++i) { q[i] = packhi(v[2*i], v[2*i+1]); q[16+i] = packlo(v[2*i], v[2*i+1]); }
    char* rp = base + row * RSB;
#pragma unroll
    for (int ch = 0; ch < 8; ++ch)
        *(uint4*)(rp + ch*16) = make_uint4(q[ch*4], q[ch*4+1], q[ch*4+2], q[ch*4+3]);
}
// B fragment value: take_hi selects hi/lo split of w
static __device__ __forceinline__ u64 bfrag(float w0, float w1, float w2, float w3, int take_hi) {
    u32 r0, r1;
    if (take_hi) { r0 = packhi(w0, w1); r1 = packhi(w2, w3); }
    else         { r0 = packlo(w0, w1); r1 = packlo(w2, w3); }
    return (u64)r0 | ((u64)r1 << 32);
}

__global__ void __launch_bounds__(128)
fused_kernel(const float* __restrict__ x, const float* __restrict__ d_all,
             const float* __restrict__ W1, const float* __restrict__ W2,
             const float* __restrict__ G1, const float* __restrict__ G2,
             const float* __restrict__ G3, float* __restrict__ out)
{
    extern __shared__ char dsm[];
    const int tid = threadIdx.x, lane = tid & 31, wid = tid >> 5;
    float* sW = (float*)(dsm + SM_W);
    u64* sB1 = (u64*)(dsm + SM_B1);
    u64* sB2 = (u64*)(dsm + SM_B2);
    u64* sB3 = (u64*)(dsm + SM_B3);

    for (int i = tid; i < 32; i += 128) sW[i] = W1[i];
    for (int i = tid; i < 48; i += 128) sW[32+i] = W2[i];
    // B fragments in mma register order; frag index f=((nt*4+kt)*2+var)
    {
        const int n = lane >> 2;
        for (int f = wid; f < 32; f += 4) {          // GEMM1: G1 [32x27->32]
            int nt = f >> 3, kt = (f >> 1) & 3, var = f & 1;
            int nn = nt*8 + n, cb = (kt*16 + (lane&3)*2) & 31;
            int th = ((kt >> 1) == var);
            float w0 = (cb   < 27) ? G1[nn*27+cb]   : 0.f;
            float w1 = (cb+1 < 27) ? G1[nn*27+cb+1] : 0.f;
            float w2 = (cb+8 < 27) ? G1[nn*27+cb+8] : 0.f;
            float w3 = (cb+9 < 27) ? G1[nn*27+cb+9] : 0.f;
            sB1[f*32+lane] = bfrag(w0, w1, w2, w3, th);
        }
        for (int f = wid; f < 64; f += 4) {          // GEMM2: G2 [64x32]
            int nt = f >> 3, kt = (f >> 1) & 3, var = f & 1;
            int nn = nt*8 + n, cb = (kt*16 + (lane&3)*2) & 31;
            int th = ((kt >> 1) == var);
            sB2[f*32+lane] = bfrag(G2[nn*32+cb], G2[nn*32+cb+1],
                                   G2[nn*32+cb+8], G2[nn*32+cb+9], th);
        }
        for (int f = wid; f < 64; f += 4) {          // GEMM3: G3 [32x64], B[k][n]=G3[k][n]
            int nt = f >> 3, kt = (f >> 1) & 3, var = f & 1;
            int nn = nt*8 + n, cb = (kt*16 + (lane&3)*2) & 31;
            int th = ((kt >> 1) == var);
            sB3[f*32+lane] = bfrag(G3[cb*64+nn], G3[(cb+1)*64+nn],
                                   G3[(cb+8)*64+nn], G3[(cb+9)*64+nn], th);
        }
    }
    __syncthreads();

    const u32 axB = su32(dsm + SM_AX), aeB = su32(dsm + SM_AE);
    const int rbase = wid * 32;

    for (int it = 0; it < TPC; ++it) {
        const int tile = blockIdx.x * TPC + it;
        const int b = (tile >= TILESB) ? 1 : 0;
        const long long vt = (long long)tile * 128 + tid - (long long)b * HWD;

        { // pack A_x row (row = tid)
            const float* xb = x + (long long)b*32*HWD + vt;
            float v[32];
#pragma unroll
            for (int c = 0; c < 32; ++c) v[c] = xb[(long long)c*HWD];
            arow(dsm + SM_AX, tid, v);
        }
        { // encode -> enc[27] -> A_e row
            const float* db = d_all + (long long)b*6*HWD + vt;
            float e[3][3];
#pragma unroll
            for (int a = 0; a < 3; ++a) {
                float dA = db[(long long)(2*a)*HWD], dB = db[(long long)(2*a+1)*HWD];
                float a0 = 0.f, a1 = 0.f, a2 = 0.f;
#pragma unroll
                for (int j = 0; j < 16; ++j) {
                    float t = fmaxf(fmaf(sW[2*j], dA, sW[2*j+1]*dB), 0.f);
                    a0 = fmaf(sW[32+j], t, a0); a1 = fmaf(sW[48+j], t, a1); a2 = fmaf(sW[64+j], t, a2);
                }
                e[a][0] = a0; e[a][1] = a1; e[a][2] = a2;
            }
            float v[32];
#pragma unroll
            for (int i = 0; i < 32; ++i) v[i] = 0.f;
#pragma unroll
            for (int i = 0; i < 3; ++i)
#pragma unroll
                for (int j = 0; j < 3; ++j) {
                    float p = e[0][i] * e[1][j];
#pragma unroll
                    for (int k = 0; k < 3; ++k) v[(i*3+j)*3+k] = p * e[2][k];
                }
            arow(dsm + SM_AE, tid, v);
        }
        __syncwarp();

        // ---- GEMM1: H = E * G1^T, relu, store back as A_h (overlay A_e) ----
        {
            u32 ae[2][4][4];
#pragma unroll
            for (int mt = 0; mt < 2; ++mt)
#pragma unroll
                for (int kt = 0; kt < 4; ++kt)
                    ldm4(ae[mt][kt], aeB + (u32)(rbase + mt*16 + (lane & 15))*RSB
                                         + kt*32 + ((lane >> 4) << 4));
            float hc[4][2][4];   // [nt][mt][reg]
#pragma unroll
            for (int nt = 0; nt < 4; ++nt) {
#pragma unroll
                for (int mt = 0; mt < 2; ++mt)
#pragma unroll
                    for (int r = 0; r < 4; ++r) hc[nt][mt][r] = 0.f;
#pragma unroll
                for (int kt = 0; kt < 4; ++kt)
#pragma unroll
                    for (int var = 0; var < 2; ++var) {
                        u64 bv = sB1[((nt*4+kt)*2+var)*32 + lane];
                        u32 b0 = (u32)bv, b1 = (u32)(bv >> 32);
                        mma16816(hc[nt][0], ae[0][kt], b0, b1);
                        mma16816(hc[nt][1], ae[1][kt], b0, b1);
                    }
            }
            __syncwarp();   // all ldmatrix reads done before overlay stores
#pragma unroll
            for (int nt = 0; nt < 4; ++nt)
#pragma unroll
                for (int mt = 0; mt < 2; ++mt) {
                    float v0 = fmaxf(hc[nt][mt][0], 0.f), v1 = fmaxf(hc[nt][mt][1], 0.f);
                    float v2 = fmaxf(hc[nt][mt][2], 0.f), v3 = fmaxf(hc[nt][mt][3], 0.f);
                    int r0 = rbase + mt*16 + (lane >> 2);
                    u32 cb = (u32)((nt*8 + (lane & 3)*2) * 2);
                    char* p0 = dsm + SM_AE + r0*RSB + cb;
                    char* p1 = dsm + SM_AE + (r0+8)*RSB + cb;
                    *(u32*)(p0)      = packhi(v0, v1);
                    *(u32*)(p0 + 64) = packlo(v0, v1);
                    *(u32*)(p1)      = packhi(v2, v3);
                    *(u32*)(p1 + 64) = packlo(v2, v3);
                }
        }
        __syncwarp();

        // ---- GEMM2 (S=H*G2^T) + GEMM3 (Y=X*G3) + epilogue ----
        {
            u32 ah[2][4][4], ax[2][4][4];
#pragma unroll
            for (int mt = 0; mt < 2; ++mt)
#pragma unroll
                for (int kt = 0; kt < 4; ++kt) {
                    u32 ro = (u32)(rbase + mt*16 + (lane & 15))*RSB + kt*32 + ((lane >> 4) << 4);
                    ldm4(ah[mt][kt], aeB + ro);
                    ldm4(ax[mt][kt], axB + ro);
                }
            float racc[2][2] = {{0.f, 0.f}, {0.f, 0.f}};
#pragma unroll
            for (int nt = 0; nt < 8; ++nt) {
                float sc[2][4], yc[2][4];
#pragma unroll
                for (int mt = 0; mt < 2; ++mt)
#pragma unroll
                    for (int r = 0; r < 4; ++r) { sc[mt][r] = 0.f; yc[mt][r] = 0.f; }
#pragma unroll
                for (int kt = 0; kt < 4; ++kt)
#pragma unroll
                    for (int var = 0; var < 2; ++var) {
                        int f = ((nt*4+kt)*2+var)*32 + lane;
                        u64 b2 = sB2[f], b3 = sB3[f];
                        mma16816(sc[0], ah[0][kt], (u32)b2, (u32)(b2 >> 32));
                        mma16816(sc[1], ah[1][kt], (u32)b2, (u32)(b2 >> 32));
                        mma16816(yc[0], ax[0][kt], (u32)b3, (u32)(b3 >> 32));
                        mma16816(yc[1], ax[1][kt], (u32)b3, (u32)(b3 >> 32));
                    }
#pragma unroll
                for (int mt = 0; mt < 2; ++mt) {
                    racc[mt][0] += fmaxf(sc[mt][0], 0.f)*yc[mt][0] + fmaxf(sc[mt][1], 0.f)*yc[mt][1];
                    racc[mt][1] += fmaxf(sc[mt][2], 0.f)*yc[mt][2] + fmaxf(sc[mt][3], 0.f)*yc[mt][3];
                }
            }
            // reduce over the 4 lanes of each quad (cols), write rows
            const long long gb = (long long)tile * 128 + rbase;
#pragma unroll
            for (int mt = 0; mt < 2; ++mt)
#pragma unroll
                for (int r = 0; r < 2; ++r) {
                    float s = racc[mt][r];
                    s += __shfl_xor_sync(0xFFFFFFFFu, s, 1);
                    s += __shfl_xor_sync(0xFFFFFFFFu, s, 2);
                    if ((lane & 3) == 0)
                        out[gb + mt*16 + (lane >> 2) + r*8] = s;
                }
        }
        __syncwarp();
    }
}

extern "C" void kernel_launch(void* const* d_in, const int* in_sizes, int n_in,
                              void* d_out, int out_size)
{
    const float* x    = (const float*)d_in[0];
    const float* dall = (const float*)d_in[1];
    const float* W1   = (const float*)d_in[2];
    const float* W2   = (const float*)d_in[3];
    const float* G1   = (const float*)d_in[4];
    const float* G2   = (const float*)d_in[5];
    const float* G3   = (const float*)d_in[6];
    float* out = (float*)d_out;

    cudaFuncSetAttribute(fused_kernel, cudaFuncAttributeMaxDynamicSharedMemorySize, SM_TOT);
    fused_kernel<<<GRID_X, 128, SM_TOT>>>(x, dall, W1, W2, G1, G2, G3, out);
}

// round 12
// speedup vs baseline: 2.0874x; 1.2239x over previous
#include <cuda_runtime.h>
#include <cuda_bf16.h>

typedef unsigned int u32; typedef unsigned short u16; typedef unsigned long long u64;

#define HWD    (96*96*96)
#define TILESB (HWD/128)     // 6912
#define TILES  (2*TILESB)    // 13824
#define TPC    8
#define GRID_X (TILES/TPC)   // 1728
#define RSB    144           // A row stride in bytes (64 bf16 + 16B pad)

// smem byte offsets — single shared A tile (X, then E, then H overlay)
#define SM_W   0
#define SM_A   1024
#define SM_B1  19456
#define SM_B2  27648
#define SM_B3  44032
#define SM_TOT 60416

static __device__ __forceinline__ u32 su32(const void* p) {
    return (u32)__cvta_generic_to_shared((void*)p);
}
static __device__ __forceinline__ void ldm4(u32* r, u32 addr) {
    asm volatile("ldmatrix.sync.aligned.m8n8.x4.shared.b16 {%0,%1,%2,%3}, [%4];"
        : "=r"(r[0]), "=r"(r[1]), "=r"(r[2]), "=r"(r[3]) : "r"(addr) : "memory");
}
static __device__ __forceinline__ void mma16816(float* c, const u32* a, u32 b0, u32 b1) {
    asm volatile("mma.sync.aligned.m16n8k16.row.col.f32.bf16.bf16.f32 "
        "{%0,%1,%2,%3}, {%4,%5,%6,%7}, {%8,%9}, {%0,%1,%2,%3};"
        : "+f"(c[0]), "+f"(c[1]), "+f"(c[2]), "+f"(c[3])
        : "r"(a[0]), "r"(a[1]), "r"(a[2]), "r"(a[3]), "r"(b0), "r"(b1));
}
static __device__ __forceinline__ u16 bhi(float v) {
    return __bfloat16_as_ushort(__float2bfloat16_rn(v));
}
static __device__ __forceinline__ u16 blo(float v) {
    float r = v - __bfloat162float(__float2bfloat16_rn(v));
    return __bfloat16_as_ushort(__float2bfloat16_rn(r));
}
static __device__ __forceinline__ u32 packhi(float a, float b) {
    return (u32)bhi(a) | ((u32)bhi(b) << 16);
}
static __device__ __forceinline__ u32 packlo(float a, float b) {
    return (u32)blo(a) | ((u32)blo(b) << 16);
}
// write one A row: [hi(v0..31) | lo(v0..31)] bf16, 8x STS.128
static __device__ __forceinline__ void arow(char* base, int row, const float* v) {
    u32 q[32];
#pragma unroll
    for (int i = 0; i < 16; ++i) { q[i] = packhi(v[2*i], v[2*i+1]); q[16+i] = packlo(v[2*i], v[2*i+1]); }
    char* rp = base + row * RSB;
#pragma unroll
    for (int ch = 0; ch < 8; ++ch)
        *(uint4*)(rp + ch*16) = make_uint4(q[ch*4], q[ch*4+1], q[ch*4+2], q[ch*4+3]);
}
static __device__ __forceinline__ u64 bfrag(float w0, float w1, float w2, float w3, int take_hi) {
    u32 r0, r1;
    if (take_hi) { r0 = packhi(w0, w1); r1 = packhi(w2, w3); }
    else         { r0 = packlo(w0, w1); r1 = packlo(w2, w3); }
    return (u64)r0 | ((u64)r1 << 32);
}

__global__ void __launch_bounds__(128)
fused_kernel(const float* __restrict__ x, const float* __restrict__ d_all,
             const float* __restrict__ W1, const float* __restrict__ W2,
             const float* __restrict__ G1, const float* __restrict__ G2,
             const float* __restrict__ G3, float* __restrict__ out)
{
    extern __shared__ char dsm[];
    const int tid = threadIdx.x, lane = tid & 31, wid = tid >> 5;
    float* sW = (float*)(dsm + SM_W);
    u64* sB1 = (u64*)(dsm + SM_B1);
    u64* sB2 = (u64*)(dsm + SM_B2);
    u64* sB3 = (u64*)(dsm + SM_B3);

    for (int i = tid; i < 32; i += 128) sW[i] = W1[i];
    for (int i = tid; i < 48; i += 128) sW[32+i] = W2[i];
    // B fragments in mma register order; frag index f=((nt*4+kt)*2+var)
    {
        const int n = lane >> 2;
        for (int f = wid; f < 32; f += 4) {          // GEMM1: G1 [32x27]
            int nt = f >> 3, kt = (f >> 1) & 3, var = f & 1;
            int nn = nt*8 + n, cb = (kt*16 + (lane&3)*2) & 31;
            int th = ((kt >> 1) == var);
            float w0 = (cb   < 27) ? G1[nn*27+cb]   : 0.f;
            float w1 = (cb+1 < 27) ? G1[nn*27+cb+1] : 0.f;
            float w2 = (cb+8 < 27) ? G1[nn*27+cb+8] : 0.f;
            float w3 = (cb+9 < 27) ? G1[nn*27+cb+9] : 0.f;
            sB1[f*32+lane] = bfrag(w0, w1, w2, w3, th);
        }
        for (int f = wid; f < 64; f += 4) {          // GEMM2: G2 [64x32]
            int nt = f >> 3, kt = (f >> 1) & 3, var = f & 1;
            int nn = nt*8 + n, cb = (kt*16 + (lane&3)*2) & 31;
            int th = ((kt >> 1) == var);
            sB2[f*32+lane] = bfrag(G2[nn*32+cb], G2[nn*32+cb+1],
                                   G2[nn*32+cb+8], G2[nn*32+cb+9], th);
        }
        for (int f = wid; f < 64; f += 4) {          // GEMM3: G3 [32x64], B[k][n]=G3[k][n]
            int nt = f >> 3, kt = (f >> 1) & 3, var = f & 1;
            int nn = nt*8 + n, cb = (kt*16 + (lane&3)*2) & 31;
            int th = ((kt >> 1) == var);
            sB3[f*32+lane] = bfrag(G3[cb*64+nn], G3[(cb+1)*64+nn],
                                   G3[(cb+8)*64+nn], G3[(cb+9)*64+nn], th);
        }
    }
    __syncthreads();

    const u32 aB = su32(dsm + SM_A);
    const int rbase = wid * 32;

    for (int it = 0; it < TPC; ++it) {
        const int tile = blockIdx.x * TPC + it;
        const int b = (tile >= TILESB) ? 1 : 0;
        const long long vt = (long long)tile * 128 + tid - (long long)b * HWD;

        // ---- pack A_x into the shared tile, pull X fragments to regs ----
        {
            const float* xb = x + (long long)b*32*HWD + vt;
            float v[32];
#pragma unroll
            for (int c = 0; c < 32; ++c) v[c] = xb[(long long)c*HWD];
            arow(dsm + SM_A, tid, v);
        }
        __syncwarp();
        u32 ax[2][4][4];
#pragma unroll
        for (int mt = 0; mt < 2; ++mt)
#pragma unroll
            for (int kt = 0; kt < 4; ++kt)
                ldm4(ax[mt][kt], aB + (u32)(rbase + mt*16 + (lane & 15))*RSB
                                    + kt*32 + ((lane >> 4) << 4));

        // ---- encode (overlaps ldmatrix drain), then overlay A_e ----
        {
            const float* db = d_all + (long long)b*6*HWD + vt;
            float e[3][3];
#pragma unroll
            for (int a = 0; a < 3; ++a) {
                float dA = db[(long long)(2*a)*HWD], dB = db[(long long)(2*a+1)*HWD];
                float a0 = 0.f, a1 = 0.f, a2 = 0.f;
#pragma unroll
                for (int j = 0; j < 16; ++j) {
                    float t = fmaxf(fmaf(sW[2*j], dA, sW[2*j+1]*dB), 0.f);
                    a0 = fmaf(sW[32+j], t, a0); a1 = fmaf(sW[48+j], t, a1); a2 = fmaf(sW[64+j], t, a2);
                }
                e[a][0] = a0; e[a][1] = a1; e[a][2] = a2;
            }
            float v[32];
#pragma unroll
            for (int i = 0; i < 32; ++i) v[i] = 0.f;
#pragma unroll
            for (int i = 0; i < 3; ++i)
#pragma unroll
                for (int j = 0; j < 3; ++j) {
                    float p = e[0][i] * e[1][j];
#pragma unroll
                    for (int k = 0; k < 3; ++k) v[(i*3+j)*3+k] = p * e[2][k];
                }
            __syncwarp();                 // all lanes' ax ldmatrix complete
            arow(dsm + SM_A, tid, v);
        }
        __syncwarp();

        // ---- GEMM1: H = E * G1^T, relu, overlay H on the tile ----
        {
            u32 ae[2][4][4];
#pragma unroll
            for (int mt = 0; mt < 2; ++mt)
#pragma unroll
                for (int kt = 0; kt < 4; ++kt)
                    ldm4(ae[mt][kt], aB + (u32)(rbase + mt*16 + (lane & 15))*RSB
                                        + kt*32 + ((lane >> 4) << 4));
            float hc[4][2][4];
#pragma unroll
            for (int nt = 0; nt < 4; ++nt) {
#pragma unroll
                for (int mt = 0; mt < 2; ++mt)
#pragma unroll
                    for (int r = 0; r < 4; ++r) hc[nt][mt][r] = 0.f;
#pragma unroll
                for (int kt = 0; kt < 4; ++kt)
#pragma unroll
                    for (int var = 0; var < 2; ++var) {
                        u64 bv = sB1[((nt*4+kt)*2+var)*32 + lane];
                        u32 b0 = (u32)bv, b1 = (u32)(bv >> 32);
                        mma16816(hc[nt][0], ae[0][kt], b0, b1);
                        mma16816(hc[nt][1], ae[1][kt], b0, b1);
                    }
            }
            __syncwarp();
#pragma unroll
            for (int nt = 0; nt < 4; ++nt)
#pragma unroll
                for (int mt = 0; mt < 2; ++mt) {
                    float v0 = fmaxf(hc[nt][mt][0], 0.f), v1 = fmaxf(hc[nt][mt][1], 0.f);
                    float v2 = fmaxf(hc[nt][mt][2], 0.f), v3 = fmaxf(hc[nt][mt][3], 0.f);
                    int r0 = rbase + mt*16 + (lane >> 2);
                    u32 cb = (u32)((nt*8 + (lane & 3)*2) * 2);
                    char* p0 = dsm + SM_A + r0*RSB + cb;
                    char* p1 = dsm + SM_A + (r0+8)*RSB + cb;
                    *(u32*)(p0)      = packhi(v0, v1);
                    *(u32*)(p0 + 64) = packlo(v0, v1);
                    *(u32*)(p1)      = packhi(v2, v3);
                    *(u32*)(p1 + 64) = packlo(v2, v3);
                }
        }
        __syncwarp();

        // ---- GEMM2 (S=H*G2^T) + GEMM3 (Y=X*G3) interleaved + epilogue ----
        {
            u32 ah[2][4][4];
#pragma unroll
            for (int mt = 0; mt < 2; ++mt)
#pragma unroll
                for (int kt = 0; kt < 4; ++kt)
                    ldm4(ah[mt][kt], aB + (u32)(rbase + mt*16 + (lane & 15))*RSB
                                        + kt*32 + ((lane >> 4) << 4));
            float racc[2][2] = {{0.f, 0.f}, {0.f, 0.f}};
#pragma unroll
            for (int nt = 0; nt < 8; ++nt) {
                float sc[2][4], yc[2][4];
#pragma unroll
                for (int mt = 0; mt < 2; ++mt)
#pragma unroll
                    for (int r = 0; r < 4; ++r) { sc[mt][r] = 0.f; yc[mt][r] = 0.f; }
#pragma unroll
                for (int kt = 0; kt < 4; ++kt)
#pragma unroll
                    for (int var = 0; var < 2; ++var) {
                        int f = ((nt*4+kt)*2+var)*32 + lane;
                        u64 b2 = sB2[f], b3 = sB3[f];
                        mma16816(sc[0], ah[0][kt], (u32)b2, (u32)(b2 >> 32));
                        mma16816(sc[1], ah[1][kt], (u32)b2, (u32)(b2 >> 32));
                        mma16816(yc[0], ax[0][kt], (u32)b3, (u32)(b3 >> 32));
                        mma16816(yc[1], ax[1][kt], (u32)b3, (u32)(b3 >> 32));
                    }
#pragma unroll
                for (int mt = 0; mt < 2; ++mt) {
                    racc[mt][0] += fmaxf(sc[mt][0], 0.f)*yc[mt][0] + fmaxf(sc[mt][1], 0.f)*yc[mt][1];
                    racc[mt][1] += fmaxf(sc[mt][2], 0.f)*yc[mt][2] + fmaxf(sc[mt][3], 0.f)*yc[mt][3];
                }
            }
            const long long gb = (long long)tile * 128 + rbase;
#pragma unroll
            for (int mt = 0; mt < 2; ++mt)
#pragma unroll
                for (int r = 0; r < 2; ++r) {
                    float s = racc[mt][r];
                    s += __shfl_xor_sync(0xFFFFFFFFu, s, 1);
                    s += __shfl_xor_sync(0xFFFFFFFFu, s, 2);
                    if ((lane & 3) == 0)
                        out[gb + mt*16 + (lane >> 2) + r*8] = s;
                }
        }
        __syncwarp();
    }
}

extern "C" void kernel_launch(void* const* d_in, const int* in_sizes, int n_in,
                              void* d_out, int out_size)
{
    const float* x    = (const float*)d_in[0];
    const float* dall = (const float*)d_in[1];
    const float* W1   = (const float*)d_in[2];
    const float* W2   = (const float*)d_in[3];
    const float* G1   = (const float*)d_in[4];
    const float* G2   = (const float*)d_in[5];
    const float* G3   = (const float*)d_in[6];
    float* out = (float*)d_out;

    cudaFuncSetAttribute(fused_kernel, cudaFuncAttributeMaxDynamicSharedMemorySize, SM_TOT);
    fused_kernel<<<GRID_X, 128, SM_TOT>>>(x, dall, W1, W2, G1, G2, G3, out);
}

// round 13
// speedup vs baseline: 2.7535x; 1.3191x over previous
#include <cuda_runtime.h>
#include <cuda_bf16.h>

typedef unsigned int u32; typedef unsigned short u16; typedef unsigned long long u64;

#define HWD    (96*96*96)
#define TILESB (HWD/128)     // 6912
#define TILES  (2*TILESB)    // 13824
#define TPC    8
#define GRID_X (TILES/TPC)   // 1728
#define RSB    144           // A row stride in bytes (64 bf16 + 16B pad)

// smem byte offsets — deduped B frags: [nt][kc][hl], 32 lanes x u64 each
#define SM_W   0
#define SM_A   1024
#define SM_B1  19456         // 16 frags = 4KB
#define SM_B2  23552         // 32 frags = 8KB
#define SM_B3  31744         // 32 frags = 8KB
#define SM_TOT 39936

static __device__ __forceinline__ u32 su32(const void* p) {
    return (u32)__cvta_generic_to_shared((void*)p);
}
static __device__ __forceinline__ void ldm4(u32* r, u32 addr) {
    asm volatile("ldmatrix.sync.aligned.m8n8.x4.shared.b16 {%0,%1,%2,%3}, [%4];"
        : "=r"(r[0]), "=r"(r[1]), "=r"(r[2]), "=r"(r[3]) : "r"(addr) : "memory");
}
static __device__ __forceinline__ void mma16816(float* c, const u32* a, u64 b) {
    asm volatile("mma.sync.aligned.m16n8k16.row.col.f32.bf16.bf16.f32 "
        "{%0,%1,%2,%3}, {%4,%5,%6,%7}, {%8,%9}, {%0,%1,%2,%3};"
        : "+f"(c[0]), "+f"(c[1]), "+f"(c[2]), "+f"(c[3])
        : "r"(a[0]), "r"(a[1]), "r"(a[2]), "r"(a[3]),
          "r"((u32)b), "r"((u32)(b >> 32)));
}
static __device__ __forceinline__ u16 bhi(float v) {
    return __bfloat16_as_ushort(__float2bfloat16_rn(v));
}
static __device__ __forceinline__ u16 blo(float v) {
    float r = v - __bfloat162float(__float2bfloat16_rn(v));
    return __bfloat16_as_ushort(__float2bfloat16_rn(r));
}
static __device__ __forceinline__ u32 packhi(float a, float b) {
    return (u32)bhi(a) | ((u32)bhi(b) << 16);
}
static __device__ __forceinline__ u32 packlo(float a, float b) {
    return (u32)blo(a) | ((u32)blo(b) << 16);
}
// write one A row: [hi(v0..31) | lo(v0..31)] bf16, 8x STS.128
static __device__ __forceinline__ void arow(char* base, int row, const float* v) {
    u32 q[32];
#pragma unroll
    for (int i = 0; i < 16; ++i) { q[i] = packhi(v[2*i], v[2*i+1]); q[16+i] = packlo(v[2*i], v[2*i+1]); }
    char* rp = base + row * RSB;
#pragma unroll
    for (int ch = 0; ch < 8; ++ch)
        *(uint4*)(rp + ch*16) = make_uint4(q[ch*4], q[ch*4+1], q[ch*4+2], q[ch*4+3]);
}
static __device__ __forceinline__ u64 bfrag(float w0, float w1, float w2, float w3, int take_hi) {
    u32 r0, r1;
    if (take_hi) { r0 = packhi(w0, w1); r1 = packhi(w2, w3); }
    else         { r0 = packlo(w0, w1); r1 = packlo(w2, w3); }
    return (u64)r0 | ((u64)r1 << 32);
}

__global__ void __launch_bounds__(128, 4)
fused_kernel(const float* __restrict__ x, const float* __restrict__ d_all,
             const float* __restrict__ W1, const float* __restrict__ W2,
             const float* __restrict__ G1, const float* __restrict__ G2,
             const float* __restrict__ G3, float* __restrict__ out)
{
    extern __shared__ char dsm[];
    const int tid = threadIdx.x, lane = tid & 31, wid = tid >> 5;
    float* sW = (float*)(dsm + SM_W);
    u64* sB1 = (u64*)(dsm + SM_B1);
    u64* sB2 = (u64*)(dsm + SM_B2);
    u64* sB3 = (u64*)(dsm + SM_B3);

    for (int i = tid; i < 32; i += 128) sW[i] = W1[i];
    for (int i = tid; i < 48; i += 128) sW[32+i] = W2[i];
    // unique B fragments: f = (nt*2+kc)*2+hl  (hl: 0=hi, 1=lo)
    {
        const int n = lane >> 2;
        for (int f = wid; f < 16; f += 4) {          // GEMM1: G1 [32x27]
            int nt = f >> 2, kc = (f >> 1) & 1, hl = f & 1;
            int nn = nt*8 + n, cb = kc*16 + (lane&3)*2;
            float w0 = (cb   < 27) ? G1[nn*27+cb]   : 0.f;
            float w1 = (cb+1 < 27) ? G1[nn*27+cb+1] : 0.f;
            float w2 = (cb+8 < 27) ? G1[nn*27+cb+8] : 0.f;
            float w3 = (cb+9 < 27) ? G1[nn*27+cb+9] : 0.f;
            sB1[f*32+lane] = bfrag(w0, w1, w2, w3, hl == 0);
        }
        for (int f = wid; f < 32; f += 4) {          // GEMM2: G2 [64x32]
            int nt = f >> 2, kc = (f >> 1) & 1, hl = f & 1;
            int nn = nt*8 + n, cb = kc*16 + (lane&3)*2;
            sB2[f*32+lane] = bfrag(G2[nn*32+cb], G2[nn*32+cb+1],
                                   G2[nn*32+cb+8], G2[nn*32+cb+9], hl == 0);
        }
        for (int f = wid; f < 32; f += 4) {          // GEMM3: G3 [32x64], B[k][n]=G3[k][n]
            int nt = f >> 2, kc = (f >> 1) & 1, hl = f & 1;
            int nn = nt*8 + n, cb = kc*16 + (lane&3)*2;
            sB3[f*32+lane] = bfrag(G3[cb*64+nn], G3[(cb+1)*64+nn],
                                   G3[(cb+8)*64+nn], G3[(cb+9)*64+nn], hl == 0);
        }
    }
    __syncthreads();

    const u32 aB = su32(dsm + SM_A);
    const int rbase = wid * 32;

    for (int it = 0; it < TPC; ++it) {
        const int tile = blockIdx.x * TPC + it;
        const int b = (tile >= TILESB) ? 1 : 0;
        const long long vt = (long long)tile * 128 + tid - (long long)b * HWD;

        // ---- pack A_x into the shared tile, pull X fragments to regs ----
        {
            const float* xb = x + (long long)b*32*HWD + vt;
            float v[32];
#pragma unroll
            for (int c = 0; c < 32; ++c) v[c] = xb[(long long)c*HWD];
            arow(dsm + SM_A, tid, v);
        }
        __syncwarp();
        u32 ax[2][4][4];                 // [mt][kt: 0,1=hi 2,3=lo][reg]
#pragma unroll
        for (int mt = 0; mt < 2; ++mt)
#pragma unroll
            for (int kt = 0; kt < 4; ++kt)
                ldm4(ax[mt][kt], aB + (u32)(rbase + mt*16 + (lane & 15))*RSB
                                    + kt*32 + ((lane >> 4) << 4));

        // ---- encode, then overlay A_e on the same tile ----
        {
            const float* db = d_all + (long long)b*6*HWD + vt;
            float e[3][3];
#pragma unroll
            for (int a = 0; a < 3; ++a) {
                float dA = db[(long long)(2*a)*HWD], dB = db[(long long)(2*a+1)*HWD];
                float a0 = 0.f, a1 = 0.f, a2 = 0.f;
#pragma unroll
                for (int j = 0; j < 16; ++j) {
                    float t = fmaxf(fmaf(sW[2*j], dA, sW[2*j+1]*dB), 0.f);
                    a0 = fmaf(sW[32+j], t, a0); a1 = fmaf(sW[48+j], t, a1); a2 = fmaf(sW[64+j], t, a2);
                }
                e[a][0] = a0; e[a][1] = a1; e[a][2] = a2;
            }
            float v[32];
#pragma unroll
            for (int i = 0; i < 32; ++i) v[i] = 0.f;
#pragma unroll
            for (int i = 0; i < 3; ++i)
#pragma unroll
                for (int j = 0; j < 3; ++j) {
                    float p = e[0][i] * e[1][j];
#pragma unroll
                    for (int k = 0; k < 3; ++k) v[(i*3+j)*3+k] = p * e[2][k];
                }
            __syncwarp();
            arow(dsm + SM_A, tid, v);
        }
        __syncwarp();

        // ---- GEMM1: H = E*G1^T (3-term split), relu, overlay H ----
        {
            u32 ae[2][4][4];
#pragma unroll
            for (int mt = 0; mt < 2; ++mt)
#pragma unroll
                for (int kt = 0; kt < 4; ++kt)
                    ldm4(ae[mt][kt], aB + (u32)(rbase + mt*16 + (lane & 15))*RSB
                                        + kt*32 + ((lane >> 4) << 4));
            float hc[4][2][4];
#pragma unroll
            for (int nt = 0; nt < 4; ++nt) {
#pragma unroll
                for (int mt = 0; mt < 2; ++mt)
#pragma unroll
                    for (int r = 0; r < 4; ++r) hc[nt][mt][r] = 0.f;
#pragma unroll
                for (int kc = 0; kc < 2; ++kc) {
                    u64 bh = sB1[((nt*2+kc)*2+0)*32 + lane];
                    u64 bl = sB1[((nt*2+kc)*2+1)*32 + lane];
                    mma16816(hc[nt][0], ae[0][kc],   bh);
                    mma16816(hc[nt][1], ae[1][kc],   bh);
                    mma16816(hc[nt][0], ae[0][kc],   bl);
                    mma16816(hc[nt][1], ae[1][kc],   bl);
                    mma16816(hc[nt][0], ae[0][kc+2], bh);
                    mma16816(hc[nt][1], ae[1][kc+2], bh);
                }
            }
            __syncwarp();
#pragma unroll
            for (int nt = 0; nt < 4; ++nt)
#pragma unroll
                for (int mt = 0; mt < 2; ++mt) {
                    float v0 = fmaxf(hc[nt][mt][0], 0.f), v1 = fmaxf(hc[nt][mt][1], 0.f);
                    float v2 = fmaxf(hc[nt][mt][2], 0.f), v3 = fmaxf(hc[nt][mt][3], 0.f);
                    int r0 = rbase + mt*16 + (lane >> 2);
                    u32 cb = (u32)((nt*8 + (lane & 3)*2) * 2);
                    char* p0 = dsm + SM_A + r0*RSB + cb;
                    char* p1 = dsm + SM_A + (r0+8)*RSB + cb;
                    *(u32*)(p0)      = packhi(v0, v1);
                    *(u32*)(p0 + 64) = packlo(v0, v1);
                    *(u32*)(p1)      = packhi(v2, v3);
                    *(u32*)(p1 + 64) = packlo(v2, v3);
                }
        }
        __syncwarp();

        // ---- GEMM2 (S=H*G2^T) + GEMM3 (Y=X*G3), 3-term, + epilogue ----
        {
            u32 ah[2][4][4];
#pragma unroll
            for (int mt = 0; mt < 2; ++mt)
#pragma unroll
                for (int kt = 0; kt < 4; ++kt)
                    ldm4(ah[mt][kt], aB + (u32)(rbase + mt*16 + (lane & 15))*RSB
                                        + kt*32 + ((lane >> 4) << 4));
            float racc[2][2] = {{0.f, 0.f}, {0.f, 0.f}};
#pragma unroll
            for (int nt = 0; nt < 8; ++nt) {
                float sc[2][4], yc[2][4];
#pragma unroll
                for (int mt = 0; mt < 2; ++mt)
#pragma unroll
                    for (int r = 0; r < 4; ++r) { sc[mt][r] = 0.f; yc[mt][r] = 0.f; }
#pragma unroll
                for (int kc = 0; kc < 2; ++kc) {
                    int fb = (nt*2+kc)*2;
                    u64 b2h = sB2[(fb+0)*32 + lane], b2l = sB2[(fb+1)*32 + lane];
                    u64 b3h = sB3[(fb+0)*32 + lane], b3l = sB3[(fb+1)*32 + lane];
                    mma16816(sc[0], ah[0][kc],   b2h);
                    mma16816(sc[1], ah[1][kc],   b2h);
                    mma16816(yc[0], ax[0][kc],   b3h);
                    mma16816(yc[1], ax[1][kc],   b3h);
                    mma16816(sc[0], ah[0][kc],   b2l);
                    mma16816(sc[1], ah[1][kc],   b2l);
                    mma16816(yc[0], ax[0][kc],   b3l);
                    mma16816(yc[1], ax[1][kc],   b3l);
                    mma16816(sc[0], ah[0][kc+2], b2h);
                    mma16816(sc[1], ah[1][kc+2], b2h);
                    mma16816(yc[0], ax[0][kc+2], b3h);
                    mma16816(yc[1], ax[1][kc+2], b3h);
                }
#pragma unroll
                for (int mt = 0; mt < 2; ++mt) {
                    racc[mt][0] += fmaxf(sc[mt][0], 0.f)*yc[mt][0] + fmaxf(sc[mt][1], 0.f)*yc[mt][1];
                    racc[mt][1] += fmaxf(sc[mt][2], 0.f)*yc[mt][2] + fmaxf(sc[mt][3], 0.f)*yc[mt][3];
                }
            }
            const long long gb = (long long)tile * 128 + rbase;
#pragma unroll
            for (int mt = 0; mt < 2; ++mt)
#pragma unroll
                for (int r = 0; r < 2; ++r) {
                    float s = racc[mt][r];
                    s += __shfl_xor_sync(0xFFFFFFFFu, s, 1);
                    s += __shfl_xor_sync(0xFFFFFFFFu, s, 2);
                    if ((lane & 3) == 0)
                        out[gb + mt*16 + (lane >> 2) + r*8] = s;
                }
        }
        __syncwarp();
    }
}

extern "C" void kernel_launch(void* const* d_in, const int* in_sizes, int n_in,
                              void* d_out, int out_size)
{
    const float* x    = (const float*)d_in[0];
    const float* dall = (const float*)d_in[1];
    const float* W1   = (const float*)d_in[2];
    const float* W2   = (const float*)d_in[3];
    const float* G1   = (const float*)d_in[4];
    const float* G2   = (const float*)d_in[5];
    const float* G3   = (const float*)d_in[6];
    float* out = (float*)d_out;

    cudaFuncSetAttribute(fused_kernel, cudaFuncAttributeMaxDynamicSharedMemorySize, SM_TOT);
    fused_kernel<<<GRID_X, 128, SM_TOT>>>(x, dall, W1, W2, G1, G2, G3, out);
}

// round 14
// speedup vs baseline: 2.8374x; 1.0305x over previous
#include <cuda_runtime.h>
#include <cuda_bf16.h>

typedef unsigned int u32; typedef unsigned short u16; typedef unsigned long long u64;

#define HWD    (96*96*96)
#define TILESB (HWD/128)     // 6912
#define TILES  (2*TILESB)    // 13824
#define TPC    8
#define GRID_X (TILES/TPC)   // 1728

// smem byte offsets; A tiles: 128 rows x 128B, XOR-swizzled
#define SM_W   0
#define SM_AX  1024
#define SM_AE  17408
#define SM_B1  33792         // 16 frags x 32 lanes x u64 = 4KB
#define SM_B2  37888         // 32 frags = 8KB
#define SM_B3  46080         // 32 frags = 8KB
#define SM_TOT 54272

static __device__ __forceinline__ u32 su32(const void* p) {
    return (u32)__cvta_generic_to_shared((void*)p);
}
static __device__ __forceinline__ void ldm4(u32* r, u32 addr) {
    asm volatile("ldmatrix.sync.aligned.m8n8.x4.shared.b16 {%0,%1,%2,%3}, [%4];"
        : "=r"(r[0]), "=r"(r[1]), "=r"(r[2]), "=r"(r[3]) : "r"(addr) : "memory");
}
static __device__ __forceinline__ void mma16816(float* c, const u32* a, u64 b) {
    asm volatile("mma.sync.aligned.m16n8k16.row.col.f32.bf16.bf16.f32 "
        "{%0,%1,%2,%3}, {%4,%5,%6,%7}, {%8,%9}, {%0,%1,%2,%3};"
        : "+f"(c[0]), "+f"(c[1]), "+f"(c[2]), "+f"(c[3])
        : "r"(a[0]), "r"(a[1]), "r"(a[2]), "r"(a[3]),
          "r"((u32)b), "r"((u32)(b >> 32)));
}
static __device__ __forceinline__ u16 bhi(float v) {
    return __bfloat16_as_ushort(__float2bfloat16_rn(v));
}
static __device__ __forceinline__ u16 blo(float v) {
    float r = v - __bfloat162float(__float2bfloat16_rn(v));
    return __bfloat16_as_ushort(__float2bfloat16_rn(r));
}
static __device__ __forceinline__ u32 packhi(float a, float b) {
    return (u32)bhi(a) | ((u32)bhi(b) << 16);
}
static __device__ __forceinline__ u32 packlo(float a, float b) {
    return (u32)blo(a) | ((u32)blo(b) << 16);
}
// one swizzled 128B row: [hi(v0..31) | lo(v0..31)] bf16, 8x STS.128
static __device__ __forceinline__ void arow_sw(char* base, int row, const float* v) {
    u32 q[32];
#pragma unroll
    for (int i = 0; i < 16; ++i) { q[i] = packhi(v[2*i], v[2*i+1]); q[16+i] = packlo(v[2*i], v[2*i+1]); }
    char* rp = base + row * 128; const int m = row & 7;
#pragma unroll
    for (int ch = 0; ch < 8; ++ch)
        *(uint4*)(rp + ((ch ^ m) * 16)) = make_uint4(q[ch*4], q[ch*4+1], q[ch*4+2], q[ch*4+3]);
}
static __device__ __forceinline__ u32 ldm_addr(u32 tileB, int row, int seg) {
    return tileB + (u32)row * 128 + (u32)((seg ^ (row & 7)) << 4);
}
static __device__ __forceinline__ u64 bfrag(float w0, float w1, float w2, float w3, int take_hi) {
    u32 r0, r1;
    if (take_hi) { r0 = packhi(w0, w1); r1 = packhi(w2, w3); }
    else         { r0 = packlo(w0, w1); r1 = packlo(w2, w3); }
    return (u64)r0 | ((u64)r1 << 32);
}

__global__ void __launch_bounds__(128, 4)
fused_kernel(const float* __restrict__ x, const float* __restrict__ d_all,
             const float* __restrict__ W1, const float* __restrict__ W2,
             const float* __restrict__ G1, const float* __restrict__ G2,
             const float* __restrict__ G3, float* __restrict__ out)
{
    extern __shared__ char dsm[];
    const int tid = threadIdx.x, lane = tid & 31, wid = tid >> 5;
    float* sW = (float*)(dsm + SM_W);
    u64* sB1 = (u64*)(dsm + SM_B1);
    u64* sB2 = (u64*)(dsm + SM_B2);
    u64* sB3 = (u64*)(dsm + SM_B3);

    for (int i = tid; i < 32; i += 128) sW[i] = W1[i];
    for (int i = tid; i < 48; i += 128) sW[32+i] = W2[i];
    // unique B fragments: f = (nt*2+kc)*2+hl  (hl: 0=hi, 1=lo)
    {
        const int n = lane >> 2;
        for (int f = wid; f < 16; f += 4) {          // GEMM1: G1 [32x27]
            int nt = f >> 2, kc = (f >> 1) & 1, hl = f & 1;
            int nn = nt*8 + n, cb = kc*16 + (lane&3)*2;
            float w0 = (cb   < 27) ? G1[nn*27+cb]   : 0.f;
            float w1 = (cb+1 < 27) ? G1[nn*27+cb+1] : 0.f;
            float w2 = (cb+8 < 27) ? G1[nn*27+cb+8] : 0.f;
            float w3 = (cb+9 < 27) ? G1[nn*27+cb+9] : 0.f;
            sB1[f*32+lane] = bfrag(w0, w1, w2, w3, hl == 0);
        }
        for (int f = wid; f < 32; f += 4) {          // GEMM2: G2 [64x32]
            int nt = f >> 2, kc = (f >> 1) & 1, hl = f & 1;
            int nn = nt*8 + n, cb = kc*16 + (lane&3)*2;
            sB2[f*32+lane] = bfrag(G2[nn*32+cb], G2[nn*32+cb+1],
                                   G2[nn*32+cb+8], G2[nn*32+cb+9], hl == 0);
        }
        for (int f = wid; f < 32; f += 4) {          // GEMM3: G3 [32x64], B[k][n]=G3[k][n]
            int nt = f >> 2, kc = (f >> 1) & 1, hl = f & 1;
            int nn = nt*8 + n, cb = kc*16 + (lane&3)*2;
            sB3[f*32+lane] = bfrag(G3[cb*64+nn], G3[(cb+1)*64+nn],
                                   G3[(cb+8)*64+nn], G3[(cb+9)*64+nn], hl == 0);
        }
    }
    __syncthreads();

    const u32 axB = su32(dsm + SM_AX), aeB = su32(dsm + SM_AE);
    const int rbase = wid * 32;

    for (int it = 0; it < TPC; ++it) {
        const int tile = blockIdx.x * TPC + it;
        const int b = (tile >= TILESB) ? 1 : 0;
        const long long vt = (long long)tile * 128 + tid - (long long)b * HWD;

        // ---- issue all global loads up front ----
        const float* xb = x + (long long)b*32*HWD + vt;
        const float* db = d_all + (long long)b*6*HWD + vt;
        float dv[6];
#pragma unroll
        for (int a = 0; a < 6; ++a) dv[a] = db[(long long)a*HWD];
        float v[32];
#pragma unroll
        for (int c = 0; c < 32; ++c) v[c] = xb[(long long)c*HWD];

        // ---- encode from dv -> enc[27] ----
        float ve[32];
        {
            float e[3][3];
#pragma unroll
            for (int a = 0; a < 3; ++a) {
                float a0 = 0.f, a1 = 0.f, a2 = 0.f;
#pragma unroll
                for (int j = 0; j < 16; ++j) {
                    float t = fmaxf(fmaf(sW[2*j], dv[2*a], sW[2*j+1]*dv[2*a+1]), 0.f);
                    a0 = fmaf(sW[32+j], t, a0); a1 = fmaf(sW[48+j], t, a1); a2 = fmaf(sW[64+j], t, a2);
                }
                e[a][0] = a0; e[a][1] = a1; e[a][2] = a2;
            }
#pragma unroll
            for (int i = 0; i < 32; ++i) ve[i] = 0.f;
#pragma unroll
            for (int i = 0; i < 3; ++i)
#pragma unroll
                for (int j = 0; j < 3; ++j) {
                    float p = e[0][i] * e[1][j];
#pragma unroll
                    for (int k = 0; k < 3; ++k) ve[(i*3+j)*3+k] = p * e[2][k];
                }
        }

        // ---- pack both tiles, one sync, both fragment loads ----
        arow_sw(dsm + SM_AE, tid, ve);
        arow_sw(dsm + SM_AX, tid, v);
        __syncwarp();
        u32 ax[2][4][4], ae[2][4][4];     // [mt][kt: 0,1=hi 2,3=lo][reg]
#pragma unroll
        for (int mt = 0; mt < 2; ++mt)
#pragma unroll
            for (int kt = 0; kt < 4; ++kt) {
                int row = rbase + mt*16 + (lane & 15), seg = kt*2 + (lane >> 4);
                ldm4(ax[mt][kt], ldm_addr(axB, row, seg));
                ldm4(ae[mt][kt], ldm_addr(aeB, row, seg));
            }

        // ---- GEMM1: H = E*G1^T (3-term), relu+pack C-frags -> A-frags ----
        u32 ah[2][4][4];
        {
            float hc[4][2][4];
#pragma unroll
            for (int nt = 0; nt < 4; ++nt) {
#pragma unroll
                for (int mt = 0; mt < 2; ++mt)
#pragma unroll
                    for (int r = 0; r < 4; ++r) hc[nt][mt][r] = 0.f;
#pragma unroll
                for (int kc = 0; kc < 2; ++kc) {
                    u64 bh = sB1[((nt*2+kc)*2+0)*32 + lane];
                    u64 bl = sB1[((nt*2+kc)*2+1)*32 + lane];
                    mma16816(hc[nt][0], ae[0][kc],   bh);
                    mma16816(hc[nt][1], ae[1][kc],   bh);
                    mma16816(hc[nt][0], ae[0][kc],   bl);
                    mma16816(hc[nt][1], ae[1][kc],   bl);
                    mma16816(hc[nt][0], ae[0][kc+2], bh);
                    mma16816(hc[nt][1], ae[1][kc+2], bh);
                }
            }
#pragma unroll
            for (int nt = 0; nt < 4; ++nt)
#pragma unroll
                for (int mt = 0; mt < 2; ++mt)
#pragma unroll
                    for (int r = 0; r < 4; ++r) hc[nt][mt][r] = fmaxf(hc[nt][mt][r], 0.f);
            // C(m16n8 of nt) -> A(k-cols 8nt..8nt+7): identical lane layout
#pragma unroll
            for (int mt = 0; mt < 2; ++mt)
#pragma unroll
                for (int kc = 0; kc < 2; ++kc) {
                    ah[mt][kc][0]   = packhi(hc[2*kc][mt][0],   hc[2*kc][mt][1]);
                    ah[mt][kc][1]   = packhi(hc[2*kc][mt][2],   hc[2*kc][mt][3]);
                    ah[mt][kc][2]   = packhi(hc[2*kc+1][mt][0], hc[2*kc+1][mt][1]);
                    ah[mt][kc][3]   = packhi(hc[2*kc+1][mt][2], hc[2*kc+1][mt][3]);
                    ah[mt][kc+2][0] = packlo(hc[2*kc][mt][0],   hc[2*kc][mt][1]);
                    ah[mt][kc+2][1] = packlo(hc[2*kc][mt][2],   hc[2*kc][mt][3]);
                    ah[mt][kc+2][2] = packlo(hc[2*kc+1][mt][0], hc[2*kc+1][mt][1]);
                    ah[mt][kc+2][3] = packlo(hc[2*kc+1][mt][2], hc[2*kc+1][mt][3]);
                }
        }

        // ---- GEMM2 (S=H*G2^T) + GEMM3 (Y=X*G3), 3-term, + epilogue ----
        {
            float racc[2][2] = {{0.f, 0.f}, {0.f, 0.f}};
#pragma unroll
            for (int nt = 0; nt < 8; ++nt) {
                float sc[2][4], yc[2][4];
#pragma unroll
                for (int mt = 0; mt < 2; ++mt)
#pragma unroll
                    for (int r = 0; r < 4; ++r) { sc[mt][r] = 0.f; yc[mt][r] = 0.f; }
#pragma unroll
                for (int kc = 0; kc < 2; ++kc) {
                    int fb = (nt*2+kc)*2;
                    u64 b2h = sB2[(fb+0)*32 + lane], b2l = sB2[(fb+1)*32 + lane];
                    u64 b3h = sB3[(fb+0)*32 + lane], b3l = sB3[(fb+1)*32 + lane];
                    mma16816(sc[0], ah[0][kc],   b2h);
                    mma16816(sc[1], ah[1][kc],   b2h);
                    mma16816(yc[0], ax[0][kc],   b3h);
                    mma16816(yc[1], ax[1][kc],   b3h);
                    mma16816(sc[0], ah[0][kc],   b2l);
                    mma16816(sc[1], ah[1][kc],   b2l);
                    mma16816(yc[0], ax[0][kc],   b3l);
                    mma16816(yc[1], ax[1][kc],   b3l);
                    mma16816(sc[0], ah[0][kc+2], b2h);
                    mma16816(sc[1], ah[1][kc+2], b2h);
                    mma16816(yc[0], ax[0][kc+2], b3h);
                    mma16816(yc[1], ax[1][kc+2], b3h);
                }
#pragma unroll
                for (int mt = 0; mt < 2; ++mt) {
                    racc[mt][0] += fmaxf(sc[mt][0], 0.f)*yc[mt][0] + fmaxf(sc[mt][1], 0.f)*yc[mt][1];
                    racc[mt][1] += fmaxf(sc[mt][2], 0.f)*yc[mt][2] + fmaxf(sc[mt][3], 0.f)*yc[mt][3];
                }
            }
            const long long gb = (long long)tile * 128 + rbase;
#pragma unroll
            for (int mt = 0; mt < 2; ++mt)
#pragma unroll
                for (int r = 0; r < 2; ++r) {
                    float s = racc[mt][r];
                    s += __shfl_xor_sync(0xFFFFFFFFu, s, 1);
                    s += __shfl_xor_sync(0xFFFFFFFFu, s, 2);
                    if ((lane & 3) == 0)
                        out[gb + mt*16 + (lane >> 2) + r*8] = s;
                }
        }
        __syncwarp();   // tile reuse hazard for next iteration
    }
}

extern "C" void kernel_launch(void* const* d_in, const int* in_sizes, int n_in,
                              void* d_out, int out_size)
{
    const float* x    = (const float*)d_in[0];
    const float* dall = (const float*)d_in[1];
    const float* W1   = (const float*)d_in[2];
    const float* W2   = (const float*)d_in[3];
    const float* G1   = (const float*)d_in[4];
    const float* G2   = (const float*)d_in[5];
    const float* G3   = (const float*)d_in[6];
    float* out = (float*)d_out;

    cudaFuncSetAttribute(fused_kernel, cudaFuncAttributeMaxDynamicSharedMemorySize, SM_TOT);
    fused_kernel<<<GRID_X, 128, SM_TOT>>>(x, dall, W1, W2, G1, G2, G3, out);
}

// round 15
// speedup vs baseline: 3.0296x; 1.0677x over previous
#include <cuda_runtime.h>
#include <cuda_bf16.h>

typedef unsigned int u32; typedef unsigned short u16; typedef unsigned long long u64;

#define HWD    (96*96*96)
#define TILESB (HWD/128)     // 6912
#define TILES  (2*TILESB)    // 13824
#define TPC    8
#define GRID_X (TILES/TPC)   // 1728

// smem byte offsets; A tiles: 128 rows x 128B, XOR-swizzled
// B frags: [nt][kc][lane][hl] -> (hi,lo) adjacent for v2.b64 loads
#define SM_W   0
#define SM_AX  1024
#define SM_AE  17408
#define SM_B1  33792         // 4KB
#define SM_B2  37888         // 8KB
#define SM_B3  46080         // 8KB
#define SM_TOT 54272

static __device__ __forceinline__ u32 su32(const void* p) {
    return (u32)__cvta_generic_to_shared((void*)p);
}
static __device__ __forceinline__ void ldm4(u32* r, u32 addr) {
    asm volatile("ldmatrix.sync.aligned.m8n8.x4.shared.b16 {%0,%1,%2,%3}, [%4];"
        : "=r"(r[0]), "=r"(r[1]), "=r"(r[2]), "=r"(r[3]) : "r"(addr) : "memory");
}
static __device__ __forceinline__ void mma16816(float* c, const u32* a, u64 b) {
    asm volatile("mma.sync.aligned.m16n8k16.row.col.f32.bf16.bf16.f32 "
        "{%0,%1,%2,%3}, {%4,%5,%6,%7}, {%8,%9}, {%0,%1,%2,%3};"
        : "+f"(c[0]), "+f"(c[1]), "+f"(c[2]), "+f"(c[3])
        : "r"(a[0]), "r"(a[1]), "r"(a[2]), "r"(a[3]),
          "r"((u32)b), "r"((u32)(b >> 32)));
}
// pair of (hi,lo) u64 B-fragments with one LDS.128
static __device__ __forceinline__ void lds2(const u64* p, u64& a, u64& b) {
    asm volatile("ld.shared.v2.b64 {%0, %1}, [%2];"
        : "=l"(a), "=l"(b) : "l"(__cvta_generic_to_shared((void*)p)));
}
// ---- rn split (weights, one-time) ----
static __device__ __forceinline__ u16 bhi(float v) {
    return __bfloat16_as_ushort(__float2bfloat16_rn(v));
}
static __device__ __forceinline__ u16 blo(float v) {
    float r = v - __bfloat162float(__float2bfloat16_rn(v));
    return __bfloat16_as_ushort(__float2bfloat16_rn(r));
}
static __device__ __forceinline__ u32 packhi(float a, float b) {
    return (u32)bhi(a) | ((u32)bhi(b) << 16);
}
static __device__ __forceinline__ u32 packlo(float a, float b) {
    return (u32)blo(a) | ((u32)blo(b) << 16);
}
static __device__ __forceinline__ u64 bfrag(float w0, float w1, float w2, float w3, int take_hi) {
    u32 r0, r1;
    if (take_hi) { r0 = packhi(w0, w1); r1 = packhi(w2, w3); }
    else         { r0 = packlo(w0, w1); r1 = packlo(w2, w3); }
    return (u64)r0 | ((u64)r1 << 32);
}
// ---- truncation split (per-tile A packs): hi = bit-chop, lo = residual ----
static __device__ __forceinline__ u32 pack_thi(float a, float b) {
    u32 d;
    asm("prmt.b32 %0, %1, %2, 0x7632;" : "=r"(d)
        : "r"(__float_as_uint(a)), "r"(__float_as_uint(b)));
    return d;   // low16 = a[31:16], high16 = b[31:16]
}
static __device__ __forceinline__ u32 pack_tlo(float a, float b) {
    float ha = __uint_as_float(__float_as_uint(a) & 0xFFFF0000u);
    float hb = __uint_as_float(__float_as_uint(b) & 0xFFFF0000u);
    __nv_bfloat162 t = __floats2bfloat162_rn(a - ha, b - hb);
    return *(u32*)&t;
}
// one swizzled 128B row: [hi(v0..31) | lo(v0..31)] bf16, 8x STS.128
static __device__ __forceinline__ void arow_sw(char* base, int row, const float* v) {
    u32 q[32];
#pragma unroll
    for (int i = 0; i < 16; ++i) {
        q[i]      = pack_thi(v[2*i], v[2*i+1]);
        q[16 + i] = pack_tlo(v[2*i], v[2*i+1]);
    }
    char* rp = base + row * 128; const int m = row & 7;
#pragma unroll
    for (int ch = 0; ch < 8; ++ch)
        *(uint4*)(rp + ((ch ^ m) * 16)) = make_uint4(q[ch*4], q[ch*4+1], q[ch*4+2], q[ch*4+3]);
}
static __device__ __forceinline__ u32 ldm_addr(u32 tileB, int row, int seg) {
    return tileB + (u32)row * 128 + (u32)((seg ^ (row & 7)) << 4);
}

__global__ void __launch_bounds__(128, 4)
fused_kernel(const float* __restrict__ x, const float* __restrict__ d_all,
             const float* __restrict__ W1, const float* __restrict__ W2,
             const float* __restrict__ G1, const float* __restrict__ G2,
             const float* __restrict__ G3, float* __restrict__ out)
{
    extern __shared__ char dsm[];
    const int tid = threadIdx.x, lane = tid & 31, wid = tid >> 5;
    float* sW = (float*)(dsm + SM_W);
    u64* sB1 = (u64*)(dsm + SM_B1);
    u64* sB2 = (u64*)(dsm + SM_B2);
    u64* sB3 = (u64*)(dsm + SM_B3);

    for (int i = tid; i < 32; i += 128) sW[i] = W1[i];
    for (int i = tid; i < 48; i += 128) sW[32+i] = W2[i];
    // B fragments: index ((nt*2+kc)*32+lane)*2 + hl  (hl: 0=hi, 1=lo)
    {
        const int n = lane >> 2;
        for (int f = wid; f < 16; f += 4) {          // GEMM1: G1 [32x27]
            int nt = f >> 2, kc = (f >> 1) & 1, hl = f & 1;
            int nn = nt*8 + n, cb = kc*16 + (lane&3)*2;
            float w0 = (cb   < 27) ? G1[nn*27+cb]   : 0.f;
            float w1 = (cb+1 < 27) ? G1[nn*27+cb+1] : 0.f;
            float w2 = (cb+8 < 27) ? G1[nn*27+cb+8] : 0.f;
            float w3 = (cb+9 < 27) ? G1[nn*27+cb+9] : 0.f;
            sB1[((nt*2+kc)*32+lane)*2 + hl] = bfrag(w0, w1, w2, w3, hl == 0);
        }
        for (int f = wid; f < 32; f += 4) {          // GEMM2: G2 [64x32]
            int nt = f >> 2, kc = (f >> 1) & 1, hl = f & 1;
            int nn = nt*8 + n, cb = kc*16 + (lane&3)*2;
            sB2[((nt*2+kc)*32+lane)*2 + hl] =
                bfrag(G2[nn*32+cb], G2[nn*32+cb+1],
                      G2[nn*32+cb+8], G2[nn*32+cb+9], hl == 0);
        }
        for (int f = wid; f < 32; f += 4) {          // GEMM3: G3 [32x64], B[k][n]=G3[k][n]
            int nt = f >> 2, kc = (f >> 1) & 1, hl = f & 1;
            int nn = nt*8 + n, cb = kc*16 + (lane&3)*2;
            sB3[((nt*2+kc)*32+lane)*2 + hl] =
                bfrag(G3[cb*64+nn], G3[(cb+1)*64+nn],
                      G3[(cb+8)*64+nn], G3[(cb+9)*64+nn], hl == 0);
        }
    }
    __syncthreads();

    const u32 axB = su32(dsm + SM_AX), aeB = su32(dsm + SM_AE);
    const int rbase = wid * 32;

    for (int it = 0; it < TPC; ++it) {
        const int tile = blockIdx.x * TPC + it;
        const int b = (tile >= TILESB) ? 1 : 0;
        const long long vt = (long long)tile * 128 + tid - (long long)b * HWD;

        // ---- issue all global loads up front ----
        const float* xb = x + (long long)b*32*HWD + vt;
        const float* db = d_all + (long long)b*6*HWD + vt;
        float dv[6];
#pragma unroll
        for (int a = 0; a < 6; ++a) dv[a] = db[(long long)a*HWD];
        float v[32];
#pragma unroll
        for (int c = 0; c < 32; ++c) v[c] = xb[(long long)c*HWD];

        // ---- encode from dv -> enc[27] ----
        float ve[32];
        {
            float e[3][3];
#pragma unroll
            for (int a = 0; a < 3; ++a) {
                float a0 = 0.f, a1 = 0.f, a2 = 0.f;
#pragma unroll
                for (int j = 0; j < 16; ++j) {
                    float t = fmaxf(fmaf(sW[2*j], dv[2*a], sW[2*j+1]*dv[2*a+1]), 0.f);
                    a0 = fmaf(sW[32+j], t, a0); a1 = fmaf(sW[48+j], t, a1); a2 = fmaf(sW[64+j], t, a2);
                }
                e[a][0] = a0; e[a][1] = a1; e[a][2] = a2;
            }
#pragma unroll
            for (int i = 0; i < 32; ++i) ve[i] = 0.f;
#pragma unroll
            for (int i = 0; i < 3; ++i)
#pragma unroll
                for (int j = 0; j < 3; ++j) {
                    float p = e[0][i] * e[1][j];
#pragma unroll
                    for (int k = 0; k < 3; ++k) ve[(i*3+j)*3+k] = p * e[2][k];
                }
        }

        // ---- pack both tiles, one sync, both fragment loads ----
        arow_sw(dsm + SM_AE, tid, ve);
        arow_sw(dsm + SM_AX, tid, v);
        __syncwarp();
        u32 ax[2][4][4], ae[2][4][4];     // [mt][kt: 0,1=hi 2,3=lo][reg]
#pragma unroll
        for (int mt = 0; mt < 2; ++mt)
#pragma unroll
            for (int kt = 0; kt < 4; ++kt) {
                int row = rbase + mt*16 + (lane & 15), seg = kt*2 + (lane >> 4);
                ldm4(ax[mt][kt], ldm_addr(axB, row, seg));
                ldm4(ae[mt][kt], ldm_addr(aeB, row, seg));
            }

        // ---- GEMM1: H = E*G1^T (3-term), relu+pack C-frags -> A-frags ----
        u32 ah[2][4][4];
        {
            float hc[4][2][4];
#pragma unroll
            for (int nt = 0; nt < 4; ++nt) {
#pragma unroll
                for (int mt = 0; mt < 2; ++mt)
#pragma unroll
                    for (int r = 0; r < 4; ++r) hc[nt][mt][r] = 0.f;
#pragma unroll
                for (int kc = 0; kc < 2; ++kc) {
                    u64 bh, bl;
                    lds2(&sB1[((nt*2+kc)*32+lane)*2], bh, bl);
                    mma16816(hc[nt][0], ae[0][kc],   bh);
                    mma16816(hc[nt][1], ae[1][kc],   bh);
                    mma16816(hc[nt][0], ae[0][kc],   bl);
                    mma16816(hc[nt][1], ae[1][kc],   bl);
                    mma16816(hc[nt][0], ae[0][kc+2], bh);
                    mma16816(hc[nt][1], ae[1][kc+2], bh);
                }
            }
#pragma unroll
            for (int nt = 0; nt < 4; ++nt)
#pragma unroll
                for (int mt = 0; mt < 2; ++mt)
#pragma unroll
                    for (int r = 0; r < 4; ++r) hc[nt][mt][r] = fmaxf(hc[nt][mt][r], 0.f);
            // C(m16n8 of nt) -> A(k-cols 8nt..8nt+7): identical lane layout
#pragma unroll
            for (int mt = 0; mt < 2; ++mt)
#pragma unroll
                for (int kc = 0; kc < 2; ++kc) {
                    ah[mt][kc][0]   = pack_thi(hc[2*kc][mt][0],   hc[2*kc][mt][1]);
                    ah[mt][kc][1]   = pack_thi(hc[2*kc][mt][2],   hc[2*kc][mt][3]);
                    ah[mt][kc][2]   = pack_thi(hc[2*kc+1][mt][0], hc[2*kc+1][mt][1]);
                    ah[mt][kc][3]   = pack_thi(hc[2*kc+1][mt][2], hc[2*kc+1][mt][3]);
                    ah[mt][kc+2][0] = pack_tlo(hc[2*kc][mt][0],   hc[2*kc][mt][1]);
                    ah[mt][kc+2][1] = pack_tlo(hc[2*kc][mt][2],   hc[2*kc][mt][3]);
                    ah[mt][kc+2][2] = pack_tlo(hc[2*kc+1][mt][0], hc[2*kc+1][mt][1]);
                    ah[mt][kc+2][3] = pack_tlo(hc[2*kc+1][mt][2], hc[2*kc+1][mt][3]);
                }
        }

        // ---- GEMM2 (S=H*G2^T) + GEMM3 (Y=X*G3), 3-term, + epilogue ----
        {
            float racc[2][2] = {{0.f, 0.f}, {0.f, 0.f}};
#pragma unroll
            for (int nt = 0; nt < 8; ++nt) {
                float sc[2][4], yc[2][4];
#pragma unroll
                for (int mt = 0; mt < 2; ++mt)
#pragma unroll
                    for (int r = 0; r < 4; ++r) { sc[mt][r] = 0.f; yc[mt][r] = 0.f; }
#pragma unroll
                for (int kc = 0; kc < 2; ++kc) {
                    u64 b2h, b2l, b3h, b3l;
                    lds2(&sB2[((nt*2+kc)*32+lane)*2], b2h, b2l);
                    lds2(&sB3[((nt*2+kc)*32+lane)*2], b3h, b3l);
                    mma16816(sc[0], ah[0][kc],   b2h);
                    mma16816(sc[1], ah[1][kc],   b2h);
                    mma16816(yc[0], ax[0][kc],   b3h);
                    mma16816(yc[1], ax[1][kc],   b3h);
                    mma16816(sc[0], ah[0][kc],   b2l);
                    mma16816(sc[1], ah[1][kc],   b2l);
                    mma16816(yc[0], ax[0][kc],   b3l);
                    mma16816(yc[1], ax[1][kc],   b3l);
                    mma16816(sc[0], ah[0][kc+2], b2h);
                    mma16816(sc[1], ah[1][kc+2], b2h);
                    mma16816(yc[0], ax[0][kc+2], b3h);
                    mma16816(yc[1], ax[1][kc+2], b3h);
                }
#pragma unroll
                for (int mt = 0; mt < 2; ++mt) {
                    racc[mt][0] += fmaxf(sc[mt][0], 0.f)*yc[mt][0] + fmaxf(sc[mt][1], 0.f)*yc[mt][1];
                    racc[mt][1] += fmaxf(sc[mt][2], 0.f)*yc[mt][2] + fmaxf(sc[mt][3], 0.f)*yc[mt][3];
                }
            }
            const long long gb = (long long)tile * 128 + rbase;
#pragma unroll
            for (int mt = 0; mt < 2; ++mt)
#pragma unroll
                for (int r = 0; r < 2; ++r) {
                    float s = racc[mt][r];
                    s += __shfl_xor_sync(0xFFFFFFFFu, s, 1);
                    s += __shfl_xor_sync(0xFFFFFFFFu, s, 2);
                    if ((lane & 3) == 0)
                        out[gb + mt*16 + (lane >> 2) + r*8] = s;
                }
        }
        __syncwarp();   // tile reuse hazard for next iteration
    }
}

extern "C" void kernel_launch(void* const* d_in, const int* in_sizes, int n_in,
                              void* d_out, int out_size)
{
    const float* x    = (const float*)d_in[0];
    const float* dall = (const float*)d_in[1];
    const float* W1   = (const float*)d_in[2];
    const float* W2   = (const float*)d_in[3];
    const float* G1   = (const float*)d_in[4];
    const float* G2   = (const float*)d_in[5];
    const float* G3   = (const float*)d_in[6];
    float* out = (float*)d_out;

    cudaFuncSetAttribute(fused_kernel, cudaFuncAttributeMaxDynamicSharedMemorySize, SM_TOT);
    fused_kernel<<<GRID_X, 128, SM_TOT>>>(x, dall, W1, W2, G1, G2, G3, out);
}

// round 16
// speedup vs baseline: 3.1516x; 1.0403x over previous
#include <cuda_runtime.h>
#include <cuda_bf16.h>

typedef unsigned int u32; typedef unsigned short u16; typedef unsigned long long u64;

#define HWD    (96*96*96)
#define TILESB (HWD/128)     // 6912 (divisible by TPC -> same batch per block)
#define TILES  (2*TILESB)    // 13824
#define TPC    8
#define GRID_X (TILES/TPC)   // 1728

// smem byte offsets; A tiles: 128 rows x 128B, XOR-swizzled
// B frags: [nt][kc][lane][hl] -> (hi,lo) adjacent for v2.b64 loads
#define SM_W   0
#define SM_AX  1024
#define SM_AE  17408
#define SM_B1  33792         // 4KB
#define SM_B2  37888         // 8KB
#define SM_B3  46080         // 8KB
#define SM_TOT 54272

static __device__ __forceinline__ u32 su32(const void* p) {
    return (u32)__cvta_generic_to_shared((void*)p);
}
static __device__ __forceinline__ void ldm4(u32* r, u32 addr) {
    asm volatile("ldmatrix.sync.aligned.m8n8.x4.shared.b16 {%0,%1,%2,%3}, [%4];"
        : "=r"(r[0]), "=r"(r[1]), "=r"(r[2]), "=r"(r[3]) : "r"(addr) : "memory");
}
static __device__ __forceinline__ void mma16816(float* c, const u32* a, u64 b) {
    asm volatile("mma.sync.aligned.m16n8k16.row.col.f32.bf16.bf16.f32 "
        "{%0,%1,%2,%3}, {%4,%5,%6,%7}, {%8,%9}, {%0,%1,%2,%3};"
        : "+f"(c[0]), "+f"(c[1]), "+f"(c[2]), "+f"(c[3])
        : "r"(a[0]), "r"(a[1]), "r"(a[2]), "r"(a[3]),
          "r"((u32)b), "r"((u32)(b >> 32)));
}
// pair of (hi,lo) u64 B-fragments with one LDS.128
static __device__ __forceinline__ void lds2(const u64* p, u64& a, u64& b) {
    asm volatile("ld.shared.v2.b64 {%0, %1}, [%2];"
        : "=l"(a), "=l"(b) : "l"(__cvta_generic_to_shared((void*)p)));
}
// ---- rn split (weights, one-time) ----
static __device__ __forceinline__ u16 bhi(float v) {
    return __bfloat16_as_ushort(__float2bfloat16_rn(v));
}
static __device__ __forceinline__ u16 blo(float v) {
    float r = v - __bfloat162float(__float2bfloat16_rn(v));
    return __bfloat16_as_ushort(__float2bfloat16_rn(r));
}
static __device__ __forceinline__ u32 packhi(float a, float b) {
    return (u32)bhi(a) | ((u32)bhi(b) << 16);
}
static __device__ __forceinline__ u32 packlo(float a, float b) {
    return (u32)blo(a) | ((u32)blo(b) << 16);
}
static __device__ __forceinline__ u64 bfrag(float w0, float w1, float w2, float w3, int take_hi) {
    u32 r0, r1;
    if (take_hi) { r0 = packhi(w0, w1); r1 = packhi(w2, w3); }
    else         { r0 = packlo(w0, w1); r1 = packlo(w2, w3); }
    return (u64)r0 | ((u64)r1 << 32);
}
// ---- truncation split (per-tile A packs): hi = bit-chop, lo = residual ----
static __device__ __forceinline__ u32 pack_thi(float a, float b) {
    u32 d;
    asm("prmt.b32 %0, %1, %2, 0x7632;" : "=r"(d)
        : "r"(__float_as_uint(a)), "r"(__float_as_uint(b)));
    return d;
}
static __device__ __forceinline__ u32 pack_tlo(float a, float b) {
    float ha = __uint_as_float(__float_as_uint(a) & 0xFFFF0000u);
    float hb = __uint_as_float(__float_as_uint(b) & 0xFFFF0000u);
    __nv_bfloat162 t = __floats2bfloat162_rn(a - ha, b - hb);
    return *(u32*)&t;
}
// one swizzled 128B row: [hi(v0..31) | lo(v0..31)] bf16, 8x STS.128
static __device__ __forceinline__ void arow_sw(char* base, int row, const float* v) {
    u32 q[32];
#pragma unroll
    for (int i = 0; i < 16; ++i) {
        q[i]      = pack_thi(v[2*i], v[2*i+1]);
        q[16 + i] = pack_tlo(v[2*i], v[2*i+1]);
    }
    char* rp = base + row * 128; const int m = row & 7;
#pragma unroll
    for (int ch = 0; ch < 8; ++ch)
        *(uint4*)(rp + ((ch ^ m) * 16)) = make_uint4(q[ch*4], q[ch*4+1], q[ch*4+2], q[ch*4+3]);
}
static __device__ __forceinline__ u32 ldm_addr(u32 tileB, int row, int seg) {
    return tileB + (u32)row * 128 + (u32)((seg ^ (row & 7)) << 4);
}

__global__ void __launch_bounds__(128, 4)
fused_kernel(const float* __restrict__ x, const float* __restrict__ d_all,
             const float* __restrict__ W1, const float* __restrict__ W2,
             const float* __restrict__ G1, const float* __restrict__ G2,
             const float* __restrict__ G3, float* __restrict__ out)
{
    extern __shared__ char dsm[];
    const int tid = threadIdx.x, lane = tid & 31, wid = tid >> 5;
    float* sW = (float*)(dsm + SM_W);
    u64* sB1 = (u64*)(dsm + SM_B1);
    u64* sB2 = (u64*)(dsm + SM_B2);
    u64* sB3 = (u64*)(dsm + SM_B3);

    for (int i = tid; i < 32; i += 128) sW[i] = W1[i];
    for (int i = tid; i < 48; i += 128) sW[32+i] = W2[i];
    // B fragments: index ((nt*2+kc)*32+lane)*2 + hl  (hl: 0=hi, 1=lo)
    {
        const int n = lane >> 2;
        for (int f = wid; f < 16; f += 4) {          // GEMM1: G1 [32x27]
            int nt = f >> 2, kc = (f >> 1) & 1, hl = f & 1;
            int nn = nt*8 + n, cb = kc*16 + (lane&3)*2;
            float w0 = (cb   < 27) ? G1[nn*27+cb]   : 0.f;
            float w1 = (cb+1 < 27) ? G1[nn*27+cb+1] : 0.f;
            float w2 = (cb+8 < 27) ? G1[nn*27+cb+8] : 0.f;
            float w3 = (cb+9 < 27) ? G1[nn*27+cb+9] : 0.f;
            sB1[((nt*2+kc)*32+lane)*2 + hl] = bfrag(w0, w1, w2, w3, hl == 0);
        }
        for (int f = wid; f < 32; f += 4) {          // GEMM2: G2 [64x32]
            int nt = f >> 2, kc = (f >> 1) & 1, hl = f & 1;
            int nn = nt*8 + n, cb = kc*16 + (lane&3)*2;
            sB2[((nt*2+kc)*32+lane)*2 + hl] =
                bfrag(G2[nn*32+cb], G2[nn*32+cb+1],
                      G2[nn*32+cb+8], G2[nn*32+cb+9], hl == 0);
        }
        for (int f = wid; f < 32; f += 4) {          // GEMM3: G3 [32x64], B[k][n]=G3[k][n]
            int nt = f >> 2, kc = (f >> 1) & 1, hl = f & 1;
            int nn = nt*8 + n, cb = kc*16 + (lane&3)*2;
            sB3[((nt*2+kc)*32+lane)*2 + hl] =
                bfrag(G3[cb*64+nn], G3[(cb+1)*64+nn],
                      G3[(cb+8)*64+nn], G3[(cb+9)*64+nn], hl == 0);
        }
    }
    __syncthreads();

    const u32 axB = su32(dsm + SM_AX), aeB = su32(dsm + SM_AE);
    const int rbase = wid * 32;

    // all 8 tiles of this block share one batch index
    const int tile0 = blockIdx.x * TPC;
    const int b = (tile0 >= TILESB) ? 1 : 0;
    const float* xbase = x + (long long)b*32*HWD - (long long)b*HWD;
    const float* dbase = d_all + (long long)b*6*HWD - (long long)b*HWD;

    // preload dv for iteration 0
    float dv[6];
    {
        const float* db = dbase + (long long)tile0*128 + tid;
#pragma unroll
        for (int a = 0; a < 6; ++a) dv[a] = db[(long long)a*HWD];
    }

    for (int it = 0; it < TPC; ++it) {
        const int tile = tile0 + it;
        const long long gvox = (long long)tile * 128 + tid;

        // ---- encode from dv -> enc[27] ----
        float ve[32];
        {
            float e[3][3];
#pragma unroll
            for (int a = 0; a < 3; ++a) {
                float a0 = 0.f, a1 = 0.f, a2 = 0.f;
#pragma unroll
                for (int j = 0; j < 16; ++j) {
                    float t = fmaxf(fmaf(sW[2*j], dv[2*a], sW[2*j+1]*dv[2*a+1]), 0.f);
                    a0 = fmaf(sW[32+j], t, a0); a1 = fmaf(sW[48+j], t, a1); a2 = fmaf(sW[64+j], t, a2);
                }
                e[a][0] = a0; e[a][1] = a1; e[a][2] = a2;
            }
#pragma unroll
            for (int i = 0; i < 32; ++i) ve[i] = 0.f;
#pragma unroll
            for (int i = 0; i < 3; ++i)
#pragma unroll
                for (int j = 0; j < 3; ++j) {
                    float p = e[0][i] * e[1][j];
#pragma unroll
                    for (int k = 0; k < 3; ++k) ve[(i*3+j)*3+k] = p * e[2][k];
                }
        }
        arow_sw(dsm + SM_AE, tid, ve);
        __syncwarp();
        u32 ae[2][4][4];
#pragma unroll
        for (int mt = 0; mt < 2; ++mt)
#pragma unroll
            for (int kt = 0; kt < 4; ++kt) {
                int row = rbase + mt*16 + (lane & 15), seg = kt*2 + (lane >> 4);
                ldm4(ae[mt][kt], ldm_addr(aeB, row, seg));
            }

        // ---- issue x loads NOW; GEMM1 hides their latency ----
        const float* xb = xbase + gvox;
        float v[32];
#pragma unroll
        for (int c = 0; c < 32; ++c) v[c] = xb[(long long)c*HWD];

        // ---- GEMM1: H = E*G1^T (3-term), relu+pack C-frags -> A-frags ----
        u32 ah[2][4][4];
        {
            float hc[4][2][4];
#pragma unroll
            for (int nt = 0; nt < 4; ++nt) {
#pragma unroll
                for (int mt = 0; mt < 2; ++mt)
#pragma unroll
                    for (int r = 0; r < 4; ++r) hc[nt][mt][r] = 0.f;
#pragma unroll
                for (int kc = 0; kc < 2; ++kc) {
                    u64 bh, bl;
                    lds2(&sB1[((nt*2+kc)*32+lane)*2], bh, bl);
                    mma16816(hc[nt][0], ae[0][kc],   bh);
                    mma16816(hc[nt][1], ae[1][kc],   bh);
                    mma16816(hc[nt][0], ae[0][kc],   bl);
                    mma16816(hc[nt][1], ae[1][kc],   bl);
                    mma16816(hc[nt][0], ae[0][kc+2], bh);
                    mma16816(hc[nt][1], ae[1][kc+2], bh);
                }
            }
#pragma unroll
            for (int nt = 0; nt < 4; ++nt)
#pragma unroll
                for (int mt = 0; mt < 2; ++mt)
#pragma unroll
                    for (int r = 0; r < 4; ++r) hc[nt][mt][r] = fmaxf(hc[nt][mt][r], 0.f);
#pragma unroll
            for (int mt = 0; mt < 2; ++mt)
#pragma unroll
                for (int kc = 0; kc < 2; ++kc) {
                    ah[mt][kc][0]   = pack_thi(hc[2*kc][mt][0],   hc[2*kc][mt][1]);
                    ah[mt][kc][1]   = pack_thi(hc[2*kc][mt][2],   hc[2*kc][mt][3]);
                    ah[mt][kc][2]   = pack_thi(hc[2*kc+1][mt][0], hc[2*kc+1][mt][1]);
                    ah[mt][kc][3]   = pack_thi(hc[2*kc+1][mt][2], hc[2*kc+1][mt][3]);
                    ah[mt][kc+2][0] = pack_tlo(hc[2*kc][mt][0],   hc[2*kc][mt][1]);
                    ah[mt][kc+2][1] = pack_tlo(hc[2*kc][mt][2],   hc[2*kc][mt][3]);
                    ah[mt][kc+2][2] = pack_tlo(hc[2*kc+1][mt][0], hc[2*kc+1][mt][1]);
                    ah[mt][kc+2][3] = pack_tlo(hc[2*kc+1][mt][2], hc[2*kc+1][mt][3]);
                }
        }

        // ---- prefetch next iteration's dv (hidden under stage 2) ----
        if (it + 1 < TPC) {
            const float* dbn = dbase + (long long)(tile + 1)*128 + tid;
#pragma unroll
            for (int a = 0; a < 6; ++a) dv[a] = dbn[(long long)a*HWD];
        }

        // ---- pack A_x (x arrived during GEMM1), load ax fragments ----
        arow_sw(dsm + SM_AX, tid, v);
        __syncwarp();
        u32 ax[2][4][4];
#pragma unroll
        for (int mt = 0; mt < 2; ++mt)
#pragma unroll
            for (int kt = 0; kt < 4; ++kt) {
                int row = rbase + mt*16 + (lane & 15), seg = kt*2 + (lane >> 4);
                ldm4(ax[mt][kt], ldm_addr(axB, row, seg));
            }

        // ---- GEMM2 (S=H*G2^T) + GEMM3 (Y=X*G3), 3-term, + epilogue ----
        {
            float racc[2][2] = {{0.f, 0.f}, {0.f, 0.f}};
#pragma unroll
            for (int nt = 0; nt < 8; ++nt) {
                float sc[2][4], yc[2][4];
#pragma unroll
                for (int mt = 0; mt < 2; ++mt)
#pragma unroll
                    for (int r = 0; r < 4; ++r) { sc[mt][r] = 0.f; yc[mt][r] = 0.f; }
#pragma unroll
                for (int kc = 0; kc < 2; ++kc) {
                    u64 b2h, b2l, b3h, b3l;
                    lds2(&sB2[((nt*2+kc)*32+lane)*2], b2h, b2l);
                    lds2(&sB3[((nt*2+kc)*32+lane)*2], b3h, b3l);
                    mma16816(sc[0], ah[0][kc],   b2h);
                    mma16816(sc[1], ah[1][kc],   b2h);
                    mma16816(yc[0], ax[0][kc],   b3h);
                    mma16816(yc[1], ax[1][kc],   b3h);
                    mma16816(sc[0], ah[0][kc],   b2l);
                    mma16816(sc[1], ah[1][kc],   b2l);
                    mma16816(yc[0], ax[0][kc],   b3l);
                    mma16816(yc[1], ax[1][kc],   b3l);
                    mma16816(sc[0], ah[0][kc+2], b2h);
                    mma16816(sc[1], ah[1][kc+2], b2h);
                    mma16816(yc[0], ax[0][kc+2], b3h);
                    mma16816(yc[1], ax[1][kc+2], b3h);
                }
#pragma unroll
                for (int mt = 0; mt < 2; ++mt) {
                    racc[mt][0] += fmaxf(sc[mt][0], 0.f)*yc[mt][0] + fmaxf(sc[mt][1], 0.f)*yc[mt][1];
                    racc[mt][1] += fmaxf(sc[mt][2], 0.f)*yc[mt][2] + fmaxf(sc[mt][3], 0.f)*yc[mt][3];
                }
            }
            const long long gb = (long long)tile * 128 + rbase;
#pragma unroll
            for (int mt = 0; mt < 2; ++mt)
#pragma unroll
                for (int r = 0; r < 2; ++r) {
                    float s = racc[mt][r];
                    s += __shfl_xor_sync(0xFFFFFFFFu, s, 1);
                    s += __shfl_xor_sync(0xFFFFFFFFu, s, 2);
                    if ((lane & 3) == 0)
                        out[gb + mt*16 + (lane >> 2) + r*8] = s;
                }
        }
        __syncwarp();   // tile reuse hazard for next iteration
    }
}

extern "C" void kernel_launch(void* const* d_in, const int* in_sizes, int n_in,
                              void* d_out, int out_size)
{
    const float* x    = (const float*)d_in[0];
    const float* dall = (const float*)d_in[1];
    const float* W1   = (const float*)d_in[2];
    const float* W2   = (const float*)d_in[3];
    const float* G1   = (const float*)d_in[4];
    const float* G2   = (const float*)d_in[5];
    const float* G3   = (const float*)d_in[6];
    float* out = (float*)d_out;

    cudaFuncSetAttribute(fused_kernel, cudaFuncAttributeMaxDynamicSharedMemorySize, SM_TOT);
    fused_kernel<<<GRID_X, 128, SM_TOT>>>(x, dall, W1, W2, G1, G2, G3, out);
}